// round 14
// baseline (speedup 1.0000x reference)
#include <cuda_runtime.h>

// LJ_8718783611256: log_prob = -(LJ pair potential + harmonic confinement)
// x: (4, 2048, 3) float32, out: (4,) float32
//
// R10: instruction-count bound. Entire inner iteration (2 packed j x 2 i-rows
// = 4 pairs) is ONE asm block using f32x2 packed math with internal .b64
// virtual regs -> no cross-statement register-pair MOV churn (R2's failure).
// Shared tile: 32B slots [x2 y2 z2 pad], ld.shared.v2.b64 + ld.shared.b64,
// warp-uniform broadcast. 548 blocks (136 tiles + harm) x4, one wave.
// Single launch, device-global accumulators + last-block finalize.

#define NB      4
#define NPTS    2048
#define IT      128          // i-rows per tile
#define JT      128          // j-cols per tile
#define TPB     256          // 64 i-groups (2 rows) x 4 j-chunks (32 j each)
#define NI      2            // i-rows per thread
#define NCHUNK  (NPTS / JT)  // 16
#define NTRI    (NCHUNK * (NCHUNK + 1) / 2)  // 136
#define NBLK    (NTRI + 1)                   // blocks per batch = 137
#define NSLOT   (JT / 2)                     // 64 packed-j slots per tile

typedef unsigned long long ull;

__device__ float g_acc[NB];          // zero-initialized at module load
__device__ unsigned int g_cnt[NB];   // zero-initialized at module load

// One packed iteration: 2 j-points (packed) x 2 i-rows = 4 pairs.
// a12/a6 accumulate d^-12 and d^-6 sums (packed lanes).
// NEG1 = (-1.0f, -1.0f): d = fma(p, -1, xi).
#define LJ_ITER_BODY(DIAG_GUARD)                                         \
    asm volatile(                                                        \
        "{\n\t"                                                          \
        ".reg .b64 px, py, pz, dd, sq, tt, i3, inv;\n\t"                 \
        ".reg .f32 s0, s1, i0, i1;\n\t"                                  \
        ".reg .pred p0, p1;\n\t"                                         \
        "ld.shared.v2.b64 {px, py}, [%10];\n\t"                          \
        "ld.shared.b64 pz, [%10+16];\n\t"                                \
        /* ---- i-row A ---- */                                          \
        "fma.rn.f32x2 dd, px, %11, %4;\n\t"                              \
        "mul.rn.f32x2 sq, dd, dd;\n\t"                                   \
        "fma.rn.f32x2 dd, py, %11, %5;\n\t"                              \
        "fma.rn.f32x2 sq, dd, dd, sq;\n\t"                               \
        "fma.rn.f32x2 dd, pz, %11, %6;\n\t"                              \
        "fma.rn.f32x2 sq, dd, dd, sq;\n\t"                               \
        "mov.b64 {s0, s1}, sq;\n\t"                                      \
        DIAG_GUARD                                                       \
        "rcp.approx.f32 i0, s0;\n\t"                                     \
        "rcp.approx.f32 i1, s1;\n\t"                                     \
        "mov.b64 inv, {i0, i1};\n\t"                                     \
        "mul.rn.f32x2 tt, inv, inv;\n\t"                                 \
        "mul.rn.f32x2 i3, tt, inv;\n\t"                                  \
        "fma.rn.f32x2 %0, i3, i3, %0;\n\t"                               \
        "add.rn.f32x2 %1, %1, i3;\n\t"                                   \
        /* ---- i-row B ---- */                                          \
        "fma.rn.f32x2 dd, px, %11, %7;\n\t"                              \
        "mul.rn.f32x2 sq, dd, dd;\n\t"                                   \
        "fma.rn.f32x2 dd, py, %11, %8;\n\t"                              \
        "fma.rn.f32x2 sq, dd, dd, sq;\n\t"                               \
        "fma.rn.f32x2 dd, pz, %11, %9;\n\t"                              \
        "fma.rn.f32x2 sq, dd, dd, sq;\n\t"                               \
        "mov.b64 {s0, s1}, sq;\n\t"                                      \
        DIAG_GUARD                                                       \
        "rcp.approx.f32 i0, s0;\n\t"                                     \
        "rcp.approx.f32 i1, s1;\n\t"                                     \
        "mov.b64 inv, {i0, i1};\n\t"                                     \
        "mul.rn.f32x2 tt, inv, inv;\n\t"                                 \
        "mul.rn.f32x2 i3, tt, inv;\n\t"                                  \
        "fma.rn.f32x2 %2, i3, i3, %2;\n\t"                               \
        "add.rn.f32x2 %3, %3, i3;\n\t"                                   \
        "}"                                                              \
        : "+l"(a12a), "+l"(a6a), "+l"(a12b), "+l"(a6b)                   \
        : "l"(xi2a), "l"(yi2a), "l"(zi2a),                               \
          "l"(xi2b), "l"(yi2b), "l"(zi2b),                               \
          "r"(addr), "l"(NEG1))

// i == j gives sq == 0 exactly; replace with huge -> rcp underflows -> 0.
#define DIAG_GUARD_STR                                                   \
        "setp.eq.f32 p0, s0, 0f00000000;\n\t"                            \
        "setp.eq.f32 p1, s1, 0f00000000;\n\t"                            \
        "selp.f32 s0, 0f7F000000, s0, p0;\n\t"                           \
        "selp.f32 s1, 0f7F000000, s1, p1;\n\t"

#define NO_GUARD_STR ""

__global__ __launch_bounds__(TPB) void lj_tri_kernel(const float* __restrict__ x,
                                                     float* __restrict__ out) {
    const int b = blockIdx.z;
    const float* xb = x + b * NPTS * 3;
    const int t = threadIdx.x;
    const int w = t >> 5, lane = t & 31;
    const ull NEG1 = 0xBF800000BF800000ULL;

    float contrib = 0.f;   // this block's contribution (thread 0 only)

    if (blockIdx.x == NBLK - 1) {
        // ---------------- harmonic block ----------------
        float sx = 0.f, sy = 0.f, sz = 0.f, s2 = 0.f;
        for (int i = t; i < NPTS; i += TPB) {
            float px = xb[3 * i + 0];
            float py = xb[3 * i + 1];
            float pz = xb[3 * i + 2];
            sx += px; sy += py; sz += pz;
            s2 = fmaf(px, px, s2);
            s2 = fmaf(py, py, s2);
            s2 = fmaf(pz, pz, s2);
        }
        #pragma unroll
        for (int o = 16; o; o >>= 1) {
            sx += __shfl_xor_sync(0xffffffffu, sx, o);
            sy += __shfl_xor_sync(0xffffffffu, sy, o);
            sz += __shfl_xor_sync(0xffffffffu, sz, o);
            s2 += __shfl_xor_sync(0xffffffffu, s2, o);
        }
        __shared__ float red[4][TPB / 32];
        if (lane == 0) { red[0][w] = sx; red[1][w] = sy; red[2][w] = sz; red[3][w] = s2; }
        __syncthreads();
        if (t == 0) {
            float tx = 0.f, ty = 0.f, tz = 0.f, t2 = 0.f;
            #pragma unroll
            for (int k = 0; k < TPB / 32; k++) {
                tx += red[0][k]; ty += red[1][k]; tz += red[2][k]; t2 += red[3][k];
            }
            float com2 = (tx * tx + ty * ty + tz * tz) * (1.0f / NPTS);
            contrib = -0.25f * (t2 - com2);  // -(0.5 * k(=0.5) * sum((x-com)^2))
        }
    } else {
        // ---------------- LJ full-tile block ----------------
        const int tid = blockIdx.x;
        int by = (int)((sqrtf(8.0f * tid + 1.0f) - 1.0f) * 0.5f);
        while ((by + 1) * (by + 2) / 2 <= tid) by++;
        while (by * (by + 1) / 2 > tid) by--;
        const int bx = tid - by * (by + 1) / 2;
        const bool diag = (bx == by);

        // shared: NSLOT slots of 32B: [x2(8) y2(8) z2(8) pad(8)]
        __shared__ __align__(16) ull sj[NSLOT * 4];
        const int j0 = bx * JT;
        if (t < JT) {
            const float* p = xb + (j0 + t) * 3;
            float* shf = (float*)sj;
            const int k = t >> 1, h = t & 1;
            shf[8 * k + 0 + h] = p[0];   // x pair
            shf[8 * k + 2 + h] = p[1];   // y pair
            shf[8 * k + 4 + h] = p[2];   // z pair
        }
        __syncthreads();

        // thread -> 2 i-rows + 32-j chunk (16 packed slots)
        const int ig = t & 63;           // i-group: rows ig*2, ig*2+1
        const int jc = t >> 6;           // j-chunk: slots jc*16 .. jc*16+15
        const int ibase = by * IT + ig * NI;

        const float* pA = xb + (ibase + 0) * 3;
        const float* pB = xb + (ibase + 1) * 3;
        ull xi2a, yi2a, zi2a, xi2b, yi2b, zi2b;
        {
            float xa = pA[0], ya = pA[1], za = pA[2];
            float xc = pB[0], yc = pB[1], zc = pB[2];
            asm("mov.b64 %0, {%1, %1};" : "=l"(xi2a) : "f"(xa));
            asm("mov.b64 %0, {%1, %1};" : "=l"(yi2a) : "f"(ya));
            asm("mov.b64 %0, {%1, %1};" : "=l"(zi2a) : "f"(za));
            asm("mov.b64 %0, {%1, %1};" : "=l"(xi2b) : "f"(xc));
            asm("mov.b64 %0, {%1, %1};" : "=l"(yi2b) : "f"(yc));
            asm("mov.b64 %0, {%1, %1};" : "=l"(zi2b) : "f"(zc));
        }

        // shared base address (32-bit shared window)
        unsigned int addr;
        asm("{ .reg .u64 a; cvta.to.shared.u64 a, %1; cvt.u32.u64 %0, a; }"
            : "=r"(addr) : "l"(sj + (size_t)jc * 16 * 4));

        ull a12a = 0ull, a6a = 0ull, a12b = 0ull, a6b = 0ull;

        if (diag) {
            #pragma unroll
            for (int k = 0; k < 16; k++) {
                LJ_ITER_BODY(DIAG_GUARD_STR);
                addr += 32;
            }
        } else {
            #pragma unroll
            for (int k = 0; k < 16; k++) {
                LJ_ITER_BODY(NO_GUARD_STR);
                addr += 32;
            }
        }

        float r12a, r12b, r6a, r6b, q12a, q12b, q6a, q6b;
        asm("mov.b64 {%0, %1}, %2;" : "=f"(r12a), "=f"(q12a) : "l"(a12a));
        asm("mov.b64 {%0, %1}, %2;" : "=f"(r6a),  "=f"(q6a)  : "l"(a6a));
        asm("mov.b64 {%0, %1}, %2;" : "=f"(r12b), "=f"(q12b) : "l"(a12b));
        asm("mov.b64 {%0, %1}, %2;" : "=f"(r6b),  "=f"(q6b)  : "l"(a6b));
        float pot = 4.0f * (((r12a + q12a) + (r12b + q12b)) -
                            ((r6a + q6a) + (r6b + q6b)));

        #pragma unroll
        for (int o = 16; o; o >>= 1)
            pot += __shfl_xor_sync(0xffffffffu, pot, o);

        __shared__ float wsum[TPB / 32];
        if (lane == 0) wsum[w] = pot;
        __syncthreads();

        if (t == 0) {
            float v = 0.f;
            #pragma unroll
            for (int k = 0; k < TPB / 32; k++) v += wsum[k];
            // off-diag tiles: each unordered pair once (weight 1);
            // diag tiles: full ordered tile (weight 0.5). Negate for log_prob.
            contrib = diag ? (-0.5f * v) : (-v);
        }
    }

    // ---------------- accumulate + last-block finalize ----------------
    if (t == 0) {
        atomicAdd(&g_acc[b], contrib);
        __threadfence();
        unsigned int done = atomicAdd(&g_cnt[b], 1u);
        if (done == NBLK - 1) {
            out[b] = g_acc[b];
            g_acc[b] = 0.f;      // reset for next graph replay
            g_cnt[b] = 0u;
        }
    }
}

extern "C" void kernel_launch(void* const* d_in, const int* in_sizes, int n_in,
                              void* d_out, int out_size) {
    const float* x = (const float*)d_in[0];
    float* out = (float*)d_out;

    dim3 grid(NBLK, 1, NB);  // 136 full tiles + 1 harmonic, x4 batches = 548
    lj_tri_kernel<<<grid, TPB>>>(x, out);
}

// round 16
// speedup vs baseline: 1.0201x; 1.0201x over previous
#include <cuda_runtime.h>

// LJ_8718783611256: log_prob = -(LJ pair potential + harmonic confinement)
// x: (4, 2048, 3) float32, out: (4,) float32
//
// R11: packed-PTX didn't change real SASS instr count (~22/pair across all
// variants). Best-known core is the scalar NI=4 loop (9.4us). Push the
// levers that DID work: NI=8 i-rows/thread (LDS + overhead amortized /8,
// 8 independent dependency chains), JCHUNK=8. Regs ~50 -> 5 blocks/SM,
// 548-block grid still one wave. Single launch, device-side finalize.

#define NB      4
#define NPTS    2048
#define IT      128          // i-rows per tile
#define JT      128          // j-cols per tile
#define TPB     256          // 16 i-groups (8 rows) x 16 j-chunks (8 j)
#define NI      8            // i-rows per thread
#define JCHUNK  8            // j-cols per thread
#define NCHUNK  (NPTS / JT)  // 16
#define NTRI    (NCHUNK * (NCHUNK + 1) / 2)  // 136
#define NBLK    (NTRI + 1)                   // blocks per batch = 137

__device__ float g_acc[NB];          // zero-initialized at module load
__device__ unsigned int g_cnt[NB];   // zero-initialized at module load

#define RCP(d, s) \
    asm("rcp.approx.f32 %0, %1;" : "=f"(d) : "f"(s))

template <bool DIAG>
__device__ __forceinline__ float lj_chunk(const float4* __restrict__ sj4,
                                          const float* xi, const float* yi,
                                          const float* zi) {
    float acc[NI];
    #pragma unroll
    for (int r = 0; r < NI; r++) acc[r] = 0.f;

    #pragma unroll
    for (int k = 0; k < JCHUNK; k++) {
        const float4 p = sj4[k];
        #pragma unroll
        for (int r = 0; r < NI; r++) {
            float dx = xi[r] - p.x;
            float dy = yi[r] - p.y;
            float dz = zi[r] - p.z;
            float sq = dx * dx;
            sq = fmaf(dy, dy, sq);
            sq = fmaf(dz, dz, sq);
            if (DIAG) {
                // i == j gives sq == 0 exactly; push to huge -> rcp -> ~0
                sq = (sq == 0.f) ? 3e38f : sq;
            }
            float inv;
            RCP(inv, sq);
            float i3 = inv * inv * inv;          // d^-6
            acc[r] += fmaf(i3, i3, -i3);         // d^-12 - d^-6
        }
    }
    float s = 0.f;
    #pragma unroll
    for (int r = 0; r < NI; r++) s += acc[r];
    return s;
}

__global__ __launch_bounds__(TPB) void lj_tri_kernel(const float* __restrict__ x,
                                                     float* __restrict__ out) {
    const int b = blockIdx.z;
    const float* xb = x + b * NPTS * 3;
    const int t = threadIdx.x;
    const int w = t >> 5, lane = t & 31;

    float contrib = 0.f;   // this block's contribution (thread 0 only)

    if (blockIdx.x == NBLK - 1) {
        // ---------------- harmonic block ----------------
        float sx = 0.f, sy = 0.f, sz = 0.f, s2 = 0.f;
        for (int i = t; i < NPTS; i += TPB) {
            float px = xb[3 * i + 0];
            float py = xb[3 * i + 1];
            float pz = xb[3 * i + 2];
            sx += px; sy += py; sz += pz;
            s2 = fmaf(px, px, s2);
            s2 = fmaf(py, py, s2);
            s2 = fmaf(pz, pz, s2);
        }
        #pragma unroll
        for (int o = 16; o; o >>= 1) {
            sx += __shfl_xor_sync(0xffffffffu, sx, o);
            sy += __shfl_xor_sync(0xffffffffu, sy, o);
            sz += __shfl_xor_sync(0xffffffffu, sz, o);
            s2 += __shfl_xor_sync(0xffffffffu, s2, o);
        }
        __shared__ float red[4][TPB / 32];
        if (lane == 0) { red[0][w] = sx; red[1][w] = sy; red[2][w] = sz; red[3][w] = s2; }
        __syncthreads();
        if (t == 0) {
            float tx = 0.f, ty = 0.f, tz = 0.f, t2 = 0.f;
            #pragma unroll
            for (int k = 0; k < TPB / 32; k++) {
                tx += red[0][k]; ty += red[1][k]; tz += red[2][k]; t2 += red[3][k];
            }
            float com2 = (tx * tx + ty * ty + tz * tz) * (1.0f / NPTS);
            contrib = -0.25f * (t2 - com2);  // -(0.5 * k(=0.5) * sum((x-com)^2))
        }
    } else {
        // ---------------- triangle tile mapping (integer only) ----------------
        const int tid = blockIdx.x;
        int by = 0;
        {
            int rem = tid;
            while (rem >= by + 1) { rem -= by + 1; by++; }
            // now tid - by*(by+1)/2 == rem
        }
        const int bx = tid - by * (by + 1) / 2;
        const bool diag = (bx == by);

        // ---------------- stage j tile as float4 ----------------
        __shared__ float4 sj[JT];
        const int j0 = bx * JT;
        if (t < JT) {
            const float* p = xb + (j0 + t) * 3;
            sj[t] = make_float4(p[0], p[1], p[2], 0.f);
        }
        __syncthreads();

        // thread -> 8 i-rows + 8-j chunk
        const int ig = t & 15;           // i-group: rows ig*8 .. ig*8+7
        const int jh = t >> 4;           // j-chunk: cols jh*8 .. jh*8+7
        const int ibase = by * IT + ig * NI;

        float xi[NI], yi[NI], zi[NI];
        #pragma unroll
        for (int r = 0; r < NI; r++) {
            const float* p = xb + (ibase + r) * 3;
            xi[r] = p[0];
            yi[r] = p[1];
            zi[r] = p[2];
        }

        const float4* sj4 = sj + jh * JCHUNK;
        float pot = diag ? lj_chunk<true>(sj4, xi, yi, zi)
                         : lj_chunk<false>(sj4, xi, yi, zi);
        pot *= 4.0f;

        #pragma unroll
        for (int o = 16; o; o >>= 1)
            pot += __shfl_xor_sync(0xffffffffu, pot, o);

        __shared__ float wsum[TPB / 32];
        if (lane == 0) wsum[w] = pot;
        __syncthreads();

        if (t == 0) {
            float v = 0.f;
            #pragma unroll
            for (int k = 0; k < TPB / 32; k++) v += wsum[k];
            // off-diag tiles: each unordered pair once (weight 1);
            // diag tiles: full ordered tile (weight 0.5). Negate for log_prob.
            contrib = diag ? (-0.5f * v) : (-v);
        }
    }

    // ---------------- accumulate + last-block finalize ----------------
    if (t == 0) {
        atomicAdd(&g_acc[b], contrib);
        __threadfence();
        unsigned int done = atomicAdd(&g_cnt[b], 1u);
        if (done == NBLK - 1) {
            out[b] = g_acc[b];
            g_acc[b] = 0.f;      // reset for next graph replay
            g_cnt[b] = 0u;
        }
    }
}

extern "C" void kernel_launch(void* const* d_in, const int* in_sizes, int n_in,
                              void* d_out, int out_size) {
    const float* x = (const float*)d_in[0];
    float* out = (float*)d_out;

    dim3 grid(NBLK, 1, NB);  // 136 full tiles + 1 harmonic, x4 batches = 548
    lj_tri_kernel<<<grid, TPB>>>(x, out);
}